// round 11
// baseline (speedup 1.0000x reference)
#include <cuda_runtime.h>
#include <math.h>
#include <stdint.h>

#define Bn  8
#define SQ  128
#define SK  128
#define IVD 32
#define DIM 32
#define EV  64
#define Hh  8
#define NH  128
#define DKd 8

typedef unsigned long long u64;

// scratch (allocation-free rule: device globals)
__device__ float g_q[Bn*SQ*EV];
__device__ float g_k[Bn*SK*EV];
__device__ unsigned long long g_bar = 0;   // monotonic ticket barrier

__device__ __forceinline__ void cp_async16(uint32_t saddr, const void* gaddr) {
    asm volatile("cp.async.cg.shared.global [%0], [%1], 16;\n"
                 :: "r"(saddr), "l"(gaddr));
}
__device__ __forceinline__ void cp_commit() {
    asm volatile("cp.async.commit_group;\n");
}
__device__ __forceinline__ void cp_wait0() {
    asm volatile("cp.async.wait_group 0;\n");
}

__device__ __forceinline__ float fast_tanh(float x) {
    x = fminf(fmaxf(x, -15.f), 15.f);
    float e = __expf(2.f * x);
    return __fdividef(e - 1.f, e + 1.f);
}

// ---- packed fp32x2 (Blackwell FFMA2; per-lane IEEE fp32) ----
__device__ __forceinline__ u64 pack2(float lo, float hi) {
    u64 r; asm("mov.b64 %0, {%1, %2};" : "=l"(r) : "f"(lo), "f"(hi)); return r;
}
__device__ __forceinline__ void unpack2(u64 v, float& lo, float& hi) {
    asm("mov.b64 {%0, %1}, %2;" : "=f"(lo), "=f"(hi) : "l"(v));
}
__device__ __forceinline__ u64 fma2(u64 a, u64 b, u64 c) {
    u64 d; asm("fma.rn.f32x2 %0, %1, %2, %3;"
               : "=l"(d) : "l"(a), "l"(b), "l"(c)); return d;
}

// ---------------------------------------------------------------------------
// Single fused kernel. 256 blocks x 256 threads, 81KB dyn smem (2 blocks/SM
// capacity -> all 256 co-resident -> grid barrier deadlock-free).
//   Stage 1: blocks [0,128)   : proj, 16 rows/block
//            blocks [128,256) : impute MLP, 8 rows/block
//   grid barrier
//   Stage 2: all blocks: attn block=(b, 4q, 8 heads) + fused out-GEMM.
// Phase B retiled: thread = (vr-pair, d-pair): each smem byte serves 4 outputs.
// ---------------------------------------------------------------------------
extern __shared__ float as[];
__global__ void __launch_bounds__(256) mega_kernel(
    const float* __restrict__ qv, const float* __restrict__ kv,
    const float* __restrict__ value, const int* __restrict__ mask,
    const float* __restrict__ w1, const float* __restrict__ b1,
    const float* __restrict__ w2,
    const float* __restrict__ wq, const float* __restrict__ bq,
    const float* __restrict__ wk, const float* __restrict__ bk,
    const float* __restrict__ wo, const float* __restrict__ bo,
    const float* __restrict__ imp,
    const float* __restrict__ wd1, const float* __restrict__ bd1,
    const float* __restrict__ lng, const float* __restrict__ lnb,
    const float* __restrict__ wd2, const float* __restrict__ bd2,
    float* __restrict__ y_out, float* __restrict__ qd_out)
{
    int t   = threadIdx.x;
    int blk = blockIdx.x;

    if (blk < 128) {
        // ========== Stage 1a: proj, 16 rows/block ==========
        float* xs_t = as;            // [i][r] 32x16 transposed, 512 f
        float* ht   = as + 512;      // [p][r] 128x16 transposed, 2048 f
        float* et   = as + 2560;     // [p][r] 64x16 transposed, 1024 f
        float* ws2  = as + 3584;     // 8192 f

        int r0 = blk * 16;                     // row in [0,2048)
        bool isQ = r0 < Bn*SQ;
        int rr0 = isQ ? r0 : r0 - Bn*SQ;
        const float* xin = isQ ? qv : kv;
        const float* wp  = isQ ? wq : wk;
        const float* bp  = isQ ? bq : bk;
        float* outp      = isQ ? g_q : g_k;

        // stage w2 (latency hidden by phase 1)
        {
            uint32_t sb = (uint32_t)__cvta_generic_to_shared(ws2);
            #pragma unroll
            for (int j = 0; j < 8; j++) {
                int idx = t + j*256;           // 2048 float4s
                cp_async16(sb + idx*16, w2 + idx*4);
            }
            cp_commit();
        }

        // load 16 input rows, transposed [i][r]
        #pragma unroll
        for (int j = 0; j < 2; j++) {
            int idx = t + j*256;               // 0..511
            int r = idx >> 5, i = idx & 31;
            xs_t[i*16 + r] = xin[rr0*IVD + idx];
        }
        __syncthreads();

        // phase 1: hidden. thread = (col c1 of 128, 8 rows), packed pairs
        {
            int c1  = t & 127;
            int rh1 = (t >> 7) * 8;
            float bb = b1[c1];
            u64 bb2 = pack2(bb, bb);
            u64 a01 = bb2, a23 = bb2, a45 = bb2, a67 = bb2;
            #pragma unroll
            for (int i = 0; i < IVD; i++) {
                float w = w1[i*NH + c1];
                u64 w2p = pack2(w, w);
                ulonglong2 x0 = *(const ulonglong2*)&xs_t[i*16 + rh1];
                ulonglong2 x1 = *(const ulonglong2*)&xs_t[i*16 + rh1 + 4];
                a01 = fma2(x0.x, w2p, a01);
                a23 = fma2(x0.y, w2p, a23);
                a45 = fma2(x1.x, w2p, a45);
                a67 = fma2(x1.y, w2p, a67);
            }
            float v0,v1,v2,v3,v4,v5,v6,v7;
            unpack2(a01, v0, v1); unpack2(a23, v2, v3);
            unpack2(a45, v4, v5); unpack2(a67, v6, v7);
            float4 h0, h1;
            h0.x = fast_tanh(v0); h0.y = fast_tanh(v1);
            h0.z = fast_tanh(v2); h0.w = fast_tanh(v3);
            h1.x = fast_tanh(v4); h1.y = fast_tanh(v5);
            h1.z = fast_tanh(v6); h1.w = fast_tanh(v7);
            *(float4*)&ht[c1*16 + rh1]     = h0;
            *(float4*)&ht[c1*16 + rh1 + 4] = h1;
        }
        cp_wait0();
        __syncthreads();

        int c  = t & 63;
        int rg = (t >> 6) * 4;        // rows rg..rg+3

        // phase 2: embed (all-smem), packed
        {
            u64 a01 = 0, a23 = 0;
            #pragma unroll 8
            for (int p = 0; p < NH; p++) {
                float w = ws2[p*EV + c];
                u64 w2p = pack2(w, w);
                ulonglong2 h = *(const ulonglong2*)&ht[p*16 + rg];
                a01 = fma2(h.x, w2p, a01);
                a23 = fma2(h.y, w2p, a23);
            }
            float o0,o1,o2,o3;
            unpack2(a01, o0, o1); unpack2(a23, o2, o3);
            float4 o; o.x=o0; o.y=o1; o.z=o2; o.w=o3;
            *(float4*)&et[c*16 + rg] = o;
        }
        __syncthreads();

        // phase 3: q/k projection, packed
        {
            float bb = bp[c];
            u64 bb2 = pack2(bb, bb);
            u64 a01 = bb2, a23 = bb2;
            #pragma unroll 8
            for (int p = 0; p < EV; p++) {
                float w = wp[p*EV + c];
                u64 w2p = pack2(w, w);
                ulonglong2 e = *(const ulonglong2*)&et[p*16 + rg];
                a01 = fma2(e.x, w2p, a01);
                a23 = fma2(e.y, w2p, a23);
            }
            float o0,o1,o2,o3;
            unpack2(a01, o0, o1); unpack2(a23, o2, o3);
            outp[(rr0+rg+0)*EV + c] = o0;
            outp[(rr0+rg+1)*EV + c] = o1;
            outp[(rr0+rg+2)*EV + c] = o2;
            outp[(rr0+rg+3)*EV + c] = o3;
        }
    } else {
        // ========== Stage 1b: impute MLP, 8 rows/block ==========
        float* xi   = as;            // [8][16] 128 f
        float* htm  = as + 128;      // [128][8] transposed, 1024 f
        float* redS = as + 1152;     // 32 f
        float* redQ = as + 1184;     // 32 f

        int row0 = (blk - 128) * 8;
        if (t < 128) xi[t] = imp[row0*16 + t];
        __syncthreads();

        int c1   = t & 127;
        int base = (t >> 7) * 4;     // rows base..base+3
        int w8   = t >> 5;
        int lane = t & 31;

        float a[4];
        {
            float bb = bd1[c1];
            #pragma unroll
            for (int j = 0; j < 4; j++) a[j] = bb;
            #pragma unroll
            for (int i = 0; i < 16; i++) {
                float w = wd1[i*NH + c1];
                #pragma unroll
                for (int j = 0; j < 4; j++)
                    a[j] = fmaf(xi[(base+j)*16 + i], w, a[j]);
            }
        }
        float ss[4], qq[4];
        #pragma unroll
        for (int j = 0; j < 4; j++) { ss[j] = a[j]; qq[j] = a[j]*a[j]; }
        #pragma unroll
        for (int off = 16; off > 0; off >>= 1) {
            #pragma unroll
            for (int j = 0; j < 4; j++) {
                ss[j] += __shfl_xor_sync(0xffffffff, ss[j], off);
                qq[j] += __shfl_xor_sync(0xffffffff, qq[j], off);
            }
        }
        if (lane == 0) {
            #pragma unroll
            for (int j = 0; j < 4; j++) { redS[w8*4+j] = ss[j]; redQ[w8*4+j] = qq[j]; }
        }
        __syncthreads();

        float g = lng[c1], be = lnb[c1];
        int gw = (base == 0) ? 0 : 4;
        {
            float4 hv; float* hp = (float*)&hv;
            #pragma unroll
            for (int j = 0; j < 4; j++) {
                float S = redS[(gw+0)*4+j] + redS[(gw+1)*4+j]
                        + redS[(gw+2)*4+j] + redS[(gw+3)*4+j];
                float Q = redQ[(gw+0)*4+j] + redQ[(gw+1)*4+j]
                        + redQ[(gw+2)*4+j] + redQ[(gw+3)*4+j];
                float mu  = S * (1.f/128.f);
                float var = Q * (1.f/128.f) - mu*mu;
                float ln = (a[j] - mu) * rsqrtf(var + 1e-5f) * g + be;
                hp[j] = fmaxf(ln, 0.f);
            }
            *(float4*)&htm[c1*8 + base] = hv;
        }
        __syncthreads();

        // GEMM2, packed row pairs
        {
            float bb = bd2[c1];
            u64 bb2 = pack2(bb, bb);
            u64 a01 = bb2, a23 = bb2;
            #pragma unroll 8
            for (int p = 0; p < NH; p++) {
                float w = wd2[p*NH + c1];
                u64 w2p = pack2(w, w);
                ulonglong2 h = *(const ulonglong2*)&htm[p*8 + base];
                a01 = fma2(h.x, w2p, a01);
                a23 = fma2(h.y, w2p, a23);
            }
            float o0,o1,o2,o3;
            unpack2(a01, o0, o1); unpack2(a23, o2, o3);
            qd_out[(row0+base+0)*NH + c1] = o0;
            qd_out[(row0+base+1)*NH + c1] = o1;
            qd_out[(row0+base+2)*NH + c1] = o2;
            qd_out[(row0+base+3)*NH + c1] = o3;
        }
    }

    // ================= grid barrier =================
    __threadfence();
    __syncthreads();
    if (t == 0) {
        unsigned long long ticket = atomicAdd(&g_bar, 1ULL);
        unsigned long long target = (ticket >> 8) * 256ULL + 256ULL;
        volatile unsigned long long* vb = &g_bar;
        while (*vb < target) { __nanosleep(64); }
        __threadfence();
    }
    __syncthreads();

    // ================= Stage 2: attn + out epilogue =================
    float* ks = as;              // 8192
    float* qs = as + 8192;       // 256
    float* mv = as + 8448;       // 4096
    float* mf = as + 12544;      // 4096
    float* es = as + 16640;      // 4096
    float* xs = mv;              // 1024 overlay after phase B

    int b  = blk >> 5;
    int q0 = (blk & 31) * 4;

    // loads (g_q/g_k via L2 to dodge stale-L1 risk across the barrier)
    {
        const float4* gk4 = (const float4*)g_k;
        float4* ks4 = (float4*)ks;
        #pragma unroll
        for (int j = 0; j < 8; j++) {
            int idx = t + j*256;               // 2048 float4s
            ks4[idx] = __ldcg(&gk4[b*2048 + idx]);
        }
        qs[t] = __ldcg(&g_q[(b*SQ + q0 + (t>>6))*EV + (t&63)]);
        const float4* v4 = (const float4*)(value + b*SK*DIM);
        const int4*   m4 = (const int4*)  (mask  + b*SK*DIM);
        float4* mv4 = (float4*)mv;
        float4* mf4 = (float4*)mf;
        #pragma unroll
        for (int j = 0; j < 4; j++) {
            int idx = t + j*256;               // 1024 float4s
            int4 mm = m4[idx]; float4 vv = v4[idx];
            float4 av, af;
            av.x = mm.x ? vv.x : 0.f;  af.x = mm.x ? 1.f : 0.f;
            av.y = mm.y ? vv.y : 0.f;  af.y = mm.y ? 1.f : 0.f;
            av.z = mm.z ? vv.z : 0.f;  af.z = mm.z ? 1.f : 0.f;
            av.w = mm.w ? vv.w : 0.f;  af.w = mm.w ? 1.f : 0.f;
            mv4[idx] = av; mf4[idx] = af;
        }
    }
    __syncthreads();

    const float scale = 0.35355339059327373f;   // 1/sqrt(8)

    // phase A: scores + softmax weights, packed dot products.
    // vr=(q,h) 0..31, kq 0..7 (16 k each)
    {
        int vr = t >> 3;
        int q = vr >> 3, h = vr & 7;
        int kbase = (t & 7) * 16;
        float4 q0r = *(const float4*)&qs[q*EV + h*DKd];
        float4 q1r = *(const float4*)&qs[q*EV + h*DKd + 4];
        u64 qp0 = pack2(q0r.x, q0r.y);
        u64 qp1 = pack2(q0r.z, q0r.w);
        u64 qp2 = pack2(q1r.x, q1r.y);
        u64 qp3 = pack2(q1r.z, q1r.w);

        float s[16];
        #pragma unroll
        for (int i = 0; i < 16; i++) {
            const ulonglong2* kp = (const ulonglong2*)&ks[(kbase+i)*EV + h*DKd];
            ulonglong2 k0 = kp[0], k1 = kp[1];
            u64 a2 = fma2(qp0, k0.x, 0ULL);
            a2 = fma2(qp1, k0.y, a2);
            a2 = fma2(qp2, k1.x, a2);
            a2 = fma2(qp3, k1.y, a2);
            float lo, hi;
            unpack2(a2, lo, hi);
            s[i] = lo + hi;
        }
        float mx = s[0];
        #pragma unroll
        for (int i = 1; i < 16; i++) mx = fmaxf(mx, s[i]);
        mx = fmaxf(mx, __shfl_xor_sync(0xffffffff, mx, 1));
        mx = fmaxf(mx, __shfl_xor_sync(0xffffffff, mx, 2));
        mx = fmaxf(mx, __shfl_xor_sync(0xffffffff, mx, 4));
        float msc = mx * scale;
        #pragma unroll
        for (int i = 0; i < 16; i++)
            es[vr*SK + kbase + i] = __expf(fmaf(s[i], scale, -msc));
    }
    __syncthreads();

    // phase B retiled: thread = (vp 0..15, ds 0..15).
    // handles vr = vp (q=vp>>3) and vr+16 (q+2), d = ds*2, ds*2+1.
    // Each LDS.64 of mv/mf feeds 2 vr x 2 d = 4 outputs -> half the smem
    // traffic of the (vr, 4d) tiling.
    int vp = t >> 4;           // 0..15
    int ds = t & 15;           // 0..15
    float2 oA, oB;
    {
        u64 numA = 0, denA = 0, numB = 0, denB = 0;
        const u64* mv2 = (const u64*)mv;       // index k*16 + ds
        const u64* mf2 = (const u64*)mf;
        const float4* eA4 = (const float4*)&es[vp*SK];
        const float4* eB4 = (const float4*)&es[(vp+16)*SK];
        #pragma unroll 4
        for (int k4 = 0; k4 < SK/4; k4++) {
            float4 ea4 = eA4[k4];
            float4 eb4 = eB4[k4];
            #pragma unroll
            for (int j = 0; j < 4; j++) {
                float ea = (j==0) ? ea4.x : (j==1) ? ea4.y : (j==2) ? ea4.z : ea4.w;
                float eb = (j==0) ? eb4.x : (j==1) ? eb4.y : (j==2) ? eb4.z : eb4.w;
                int k = k4*4 + j;
                u64 v2 = mv2[k*16 + ds];
                u64 f2 = mf2[k*16 + ds];
                u64 e2a = pack2(ea, ea);
                u64 e2b = pack2(eb, eb);
                numA = fma2(e2a, v2, numA);
                denA = fma2(e2a, f2, denA);
                numB = fma2(e2b, v2, numB);
                denB = fma2(e2b, f2, denB);
            }
        }
        float na0,na1, da0,da1, nb0,nb1, db0,db1;
        unpack2(numA, na0, na1); unpack2(denA, da0, da1);
        unpack2(numB, nb0, nb1); unpack2(denB, db0, db1);
        oA.x = __fdividef(na0, da0); oA.y = __fdividef(na1, da1);
        oB.x = __fdividef(nb0, db0); oB.y = __fdividef(nb1, db1);
    }
    __syncthreads();    // mv/mf reads done; safe to overlay xs
    {
        int qa = vp >> 3, h = vp & 7;          // vr = vp
        *(float2*)&xs[qa*256 + h*DIM + ds*2]       = oA;
        *(float2*)&xs[(qa+2)*256 + h*DIM + ds*2]   = oB;   // vr = vp+16
    }
    __syncthreads();

    // epilogue: y[q][c] = sum_p xs[q][p] * wo[p][c] + bo[c]
    // thread = (col pair cp, row qsel); packed col-pair FMA, LDG.64 wo.
    {
        int cp   = (t & 63) * 2;
        int qsel = t >> 6;            // 0..3
        u64 acc = pack2(bo[cp], bo[cp+1]);
        const float* xp = &xs[qsel*256];
        #pragma unroll 8
        for (int p = 0; p < 256; p++) {
            u64 w2p = *(const u64*)&wo[p*NH + cp];
            u64 x2  = pack2(xp[p], xp[p]);
            acc = fma2(x2, w2p, acc);
        }
        float r0v, r1v;
        unpack2(acc, r0v, r1v);
        float2 o; o.x = r0v; o.y = r1v;
        *(float2*)&y_out[(b*SQ + q0 + qsel)*NH + cp] = o;
    }
}

// ---------------------------------------------------------------------------
extern "C" void kernel_launch(void* const* d_in, const int* in_sizes, int n_in,
                              void* d_out, int out_size)
{
    bool dictOrder = (in_sizes[4] == Bn*SK*DIM);

    const float *qv, *kv, *val, *imp, *w1, *b1, *w2, *wq, *bq, *wk, *bk,
                *wo, *bo, *wd1, *bd1, *lng, *lnb, *wd2, *bd2;
    const int* mask;

    if (dictOrder) {
        qv  = (const float*)d_in[0];  kv  = (const float*)d_in[1];
        val = (const float*)d_in[2];  imp = (const float*)d_in[3];
        mask= (const int*)  d_in[4];
        w1  = (const float*)d_in[5];  b1  = (const float*)d_in[6];
        w2  = (const float*)d_in[7];
        wq  = (const float*)d_in[8];  bq  = (const float*)d_in[9];
        wk  = (const float*)d_in[10]; bk  = (const float*)d_in[11];
        wo  = (const float*)d_in[12]; bo  = (const float*)d_in[13];
        wd1 = (const float*)d_in[14]; bd1 = (const float*)d_in[15];
        lng = (const float*)d_in[16]; lnb = (const float*)d_in[17];
        wd2 = (const float*)d_in[18]; bd2 = (const float*)d_in[19];
    } else {
        qv  = (const float*)d_in[0];  kv  = (const float*)d_in[1];
        val = (const float*)d_in[2];  imp = (const float*)d_in[3];
        w1  = (const float*)d_in[4];  b1  = (const float*)d_in[5];
        w2  = (const float*)d_in[6];
        wq  = (const float*)d_in[7];  bq  = (const float*)d_in[8];
        wk  = (const float*)d_in[9];  bk  = (const float*)d_in[10];
        wo  = (const float*)d_in[11]; bo  = (const float*)d_in[12];
        wd1 = (const float*)d_in[13]; bd1 = (const float*)d_in[14];
        lng = (const float*)d_in[15]; lnb = (const float*)d_in[16];
        wd2 = (const float*)d_in[17]; bd2 = (const float*)d_in[18];
        mask= (const int*)  d_in[19];
    }

    float* y  = (float*)d_out;                       // [8,128,128]
    float* qd = (float*)d_out + Bn*SQ*NH;            // [8,128,128]

    cudaFuncSetAttribute(mega_kernel,
                         cudaFuncAttributeMaxDynamicSharedMemorySize,
                         20736 * sizeof(float));

    mega_kernel<<<256, 256, 20736 * sizeof(float)>>>(
        qv, kv, val, mask, w1, b1, w2, wq, bq, wk, bk, wo, bo,
        imp, wd1, bd1, lng, lnb, wd2, bd2, y, qd);
}

// round 12
// speedup vs baseline: 1.2493x; 1.2493x over previous
#include <cuda_runtime.h>
#include <math.h>
#include <stdint.h>

#define Bn  8
#define SQ  128
#define SK  128
#define IVD 32
#define DIM 32
#define EV  64
#define Hh  8
#define NH  128
#define DKd 8

typedef unsigned long long u64;

// scratch (allocation-free rule: device globals)
__device__ float g_q[Bn*SQ*EV];
__device__ float g_k[Bn*SK*EV];
__device__ unsigned long long g_bar = 0;   // monotonic ticket barrier

__device__ __forceinline__ void cp_async16(uint32_t saddr, const void* gaddr) {
    asm volatile("cp.async.cg.shared.global [%0], [%1], 16;\n"
                 :: "r"(saddr), "l"(gaddr));
}
__device__ __forceinline__ void cp_commit() {
    asm volatile("cp.async.commit_group;\n");
}
__device__ __forceinline__ void cp_wait0() {
    asm volatile("cp.async.wait_group 0;\n");
}

__device__ __forceinline__ float fast_tanh(float x) {
    x = fminf(fmaxf(x, -15.f), 15.f);
    float e = __expf(2.f * x);
    return __fdividef(e - 1.f, e + 1.f);
}

// ---- packed fp32x2 (Blackwell FFMA2; per-lane IEEE fp32) ----
__device__ __forceinline__ u64 pack2(float lo, float hi) {
    u64 r; asm("mov.b64 %0, {%1, %2};" : "=l"(r) : "f"(lo), "f"(hi)); return r;
}
__device__ __forceinline__ void unpack2(u64 v, float& lo, float& hi) {
    asm("mov.b64 {%0, %1}, %2;" : "=f"(lo), "=f"(hi) : "l"(v));
}
__device__ __forceinline__ u64 fma2(u64 a, u64 b, u64 c) {
    u64 d; asm("fma.rn.f32x2 %0, %1, %2, %3;"
               : "=l"(d) : "l"(a), "l"(b), "l"(c)); return d;
}
__device__ __forceinline__ u64 add2(u64 a, u64 b) {
    u64 d; asm("add.rn.f32x2 %0, %1, %2;" : "=l"(d) : "l"(a), "l"(b)); return d;
}

// ---------------------------------------------------------------------------
// Single fused kernel. 256 blocks x 256 threads, 81KB dyn smem (2 blocks/SM
// capacity -> all 256 co-resident -> grid barrier deadlock-free).
//   Stage 1: blocks [0,128)   : proj, 16 rows/block
//            blocks [128,256) : impute MLP, 8 rows/block
//   grid barrier
//   Stage 2: all blocks: attn block=(b, 4q, 8 heads) + fused out-GEMM.
// Epilogue: 4 independent packed accumulator chains (breaks the 256-link
// serial FMA chain; keeps ~32 wo LDGs in flight).
// ---------------------------------------------------------------------------
extern __shared__ float as[];
__global__ void __launch_bounds__(256) mega_kernel(
    const float* __restrict__ qv, const float* __restrict__ kv,
    const float* __restrict__ value, const int* __restrict__ mask,
    const float* __restrict__ w1, const float* __restrict__ b1,
    const float* __restrict__ w2,
    const float* __restrict__ wq, const float* __restrict__ bq,
    const float* __restrict__ wk, const float* __restrict__ bk,
    const float* __restrict__ wo, const float* __restrict__ bo,
    const float* __restrict__ imp,
    const float* __restrict__ wd1, const float* __restrict__ bd1,
    const float* __restrict__ lng, const float* __restrict__ lnb,
    const float* __restrict__ wd2, const float* __restrict__ bd2,
    float* __restrict__ y_out, float* __restrict__ qd_out)
{
    int t   = threadIdx.x;
    int blk = blockIdx.x;

    if (blk < 128) {
        // ========== Stage 1a: proj, 16 rows/block ==========
        float* xs_t = as;            // [i][r] 32x16 transposed, 512 f
        float* ht   = as + 512;      // [p][r] 128x16 transposed, 2048 f
        float* et   = as + 2560;     // [p][r] 64x16 transposed, 1024 f
        float* ws2  = as + 3584;     // 8192 f

        int r0 = blk * 16;                     // row in [0,2048)
        bool isQ = r0 < Bn*SQ;
        int rr0 = isQ ? r0 : r0 - Bn*SQ;
        const float* xin = isQ ? qv : kv;
        const float* wp  = isQ ? wq : wk;
        const float* bp  = isQ ? bq : bk;
        float* outp      = isQ ? g_q : g_k;

        // stage w2 (latency hidden by phase 1)
        {
            uint32_t sb = (uint32_t)__cvta_generic_to_shared(ws2);
            #pragma unroll
            for (int j = 0; j < 8; j++) {
                int idx = t + j*256;           // 2048 float4s
                cp_async16(sb + idx*16, w2 + idx*4);
            }
            cp_commit();
        }

        // load 16 input rows, transposed [i][r]
        #pragma unroll
        for (int j = 0; j < 2; j++) {
            int idx = t + j*256;               // 0..511
            int r = idx >> 5, i = idx & 31;
            xs_t[i*16 + r] = xin[rr0*IVD + idx];
        }
        __syncthreads();

        // phase 1: hidden. thread = (col c1 of 128, 8 rows), packed pairs
        {
            int c1  = t & 127;
            int rh1 = (t >> 7) * 8;
            float bb = b1[c1];
            u64 bb2 = pack2(bb, bb);
            u64 a01 = bb2, a23 = bb2, a45 = bb2, a67 = bb2;
            #pragma unroll
            for (int i = 0; i < IVD; i++) {
                float w = w1[i*NH + c1];
                u64 w2p = pack2(w, w);
                ulonglong2 x0 = *(const ulonglong2*)&xs_t[i*16 + rh1];
                ulonglong2 x1 = *(const ulonglong2*)&xs_t[i*16 + rh1 + 4];
                a01 = fma2(x0.x, w2p, a01);
                a23 = fma2(x0.y, w2p, a23);
                a45 = fma2(x1.x, w2p, a45);
                a67 = fma2(x1.y, w2p, a67);
            }
            float v0,v1,v2,v3,v4,v5,v6,v7;
            unpack2(a01, v0, v1); unpack2(a23, v2, v3);
            unpack2(a45, v4, v5); unpack2(a67, v6, v7);
            float4 h0, h1;
            h0.x = fast_tanh(v0); h0.y = fast_tanh(v1);
            h0.z = fast_tanh(v2); h0.w = fast_tanh(v3);
            h1.x = fast_tanh(v4); h1.y = fast_tanh(v5);
            h1.z = fast_tanh(v6); h1.w = fast_tanh(v7);
            *(float4*)&ht[c1*16 + rh1]     = h0;
            *(float4*)&ht[c1*16 + rh1 + 4] = h1;
        }
        cp_wait0();
        __syncthreads();

        int c  = t & 63;
        int rg = (t >> 6) * 4;        // rows rg..rg+3

        // phase 2: embed (all-smem), packed
        {
            u64 a01 = 0, a23 = 0;
            #pragma unroll 8
            for (int p = 0; p < NH; p++) {
                float w = ws2[p*EV + c];
                u64 w2p = pack2(w, w);
                ulonglong2 h = *(const ulonglong2*)&ht[p*16 + rg];
                a01 = fma2(h.x, w2p, a01);
                a23 = fma2(h.y, w2p, a23);
            }
            float o0,o1,o2,o3;
            unpack2(a01, o0, o1); unpack2(a23, o2, o3);
            float4 o; o.x=o0; o.y=o1; o.z=o2; o.w=o3;
            *(float4*)&et[c*16 + rg] = o;
        }
        __syncthreads();

        // phase 3: q/k projection, packed
        {
            float bb = bp[c];
            u64 bb2 = pack2(bb, bb);
            u64 a01 = bb2, a23 = bb2;
            #pragma unroll 8
            for (int p = 0; p < EV; p++) {
                float w = wp[p*EV + c];
                u64 w2p = pack2(w, w);
                ulonglong2 e = *(const ulonglong2*)&et[p*16 + rg];
                a01 = fma2(e.x, w2p, a01);
                a23 = fma2(e.y, w2p, a23);
            }
            float o0,o1,o2,o3;
            unpack2(a01, o0, o1); unpack2(a23, o2, o3);
            outp[(rr0+rg+0)*EV + c] = o0;
            outp[(rr0+rg+1)*EV + c] = o1;
            outp[(rr0+rg+2)*EV + c] = o2;
            outp[(rr0+rg+3)*EV + c] = o3;
        }
    } else {
        // ========== Stage 1b: impute MLP, 8 rows/block ==========
        float* xi   = as;            // [8][16] 128 f
        float* htm  = as + 128;      // [128][8] transposed, 1024 f
        float* redS = as + 1152;     // 32 f
        float* redQ = as + 1184;     // 32 f

        int row0 = (blk - 128) * 8;
        if (t < 128) xi[t] = imp[row0*16 + t];
        __syncthreads();

        int c1   = t & 127;
        int base = (t >> 7) * 4;     // rows base..base+3
        int w8   = t >> 5;
        int lane = t & 31;

        float a[4];
        {
            float bb = bd1[c1];
            #pragma unroll
            for (int j = 0; j < 4; j++) a[j] = bb;
            #pragma unroll
            for (int i = 0; i < 16; i++) {
                float w = wd1[i*NH + c1];
                #pragma unroll
                for (int j = 0; j < 4; j++)
                    a[j] = fmaf(xi[(base+j)*16 + i], w, a[j]);
            }
        }
        float ss[4], qq[4];
        #pragma unroll
        for (int j = 0; j < 4; j++) { ss[j] = a[j]; qq[j] = a[j]*a[j]; }
        #pragma unroll
        for (int off = 16; off > 0; off >>= 1) {
            #pragma unroll
            for (int j = 0; j < 4; j++) {
                ss[j] += __shfl_xor_sync(0xffffffff, ss[j], off);
                qq[j] += __shfl_xor_sync(0xffffffff, qq[j], off);
            }
        }
        if (lane == 0) {
            #pragma unroll
            for (int j = 0; j < 4; j++) { redS[w8*4+j] = ss[j]; redQ[w8*4+j] = qq[j]; }
        }
        __syncthreads();

        float g = lng[c1], be = lnb[c1];
        int gw = (base == 0) ? 0 : 4;
        {
            float4 hv; float* hp = (float*)&hv;
            #pragma unroll
            for (int j = 0; j < 4; j++) {
                float S = redS[(gw+0)*4+j] + redS[(gw+1)*4+j]
                        + redS[(gw+2)*4+j] + redS[(gw+3)*4+j];
                float Q = redQ[(gw+0)*4+j] + redQ[(gw+1)*4+j]
                        + redQ[(gw+2)*4+j] + redQ[(gw+3)*4+j];
                float mu  = S * (1.f/128.f);
                float var = Q * (1.f/128.f) - mu*mu;
                float ln = (a[j] - mu) * rsqrtf(var + 1e-5f) * g + be;
                hp[j] = fmaxf(ln, 0.f);
            }
            *(float4*)&htm[c1*8 + base] = hv;
        }
        __syncthreads();

        // GEMM2, packed row pairs
        {
            float bb = bd2[c1];
            u64 bb2 = pack2(bb, bb);
            u64 a01 = bb2, a23 = bb2;
            #pragma unroll 8
            for (int p = 0; p < NH; p++) {
                float w = wd2[p*NH + c1];
                u64 w2p = pack2(w, w);
                ulonglong2 h = *(const ulonglong2*)&htm[p*8 + base];
                a01 = fma2(h.x, w2p, a01);
                a23 = fma2(h.y, w2p, a23);
            }
            float o0,o1,o2,o3;
            unpack2(a01, o0, o1); unpack2(a23, o2, o3);
            qd_out[(row0+base+0)*NH + c1] = o0;
            qd_out[(row0+base+1)*NH + c1] = o1;
            qd_out[(row0+base+2)*NH + c1] = o2;
            qd_out[(row0+base+3)*NH + c1] = o3;
        }
    }

    // ================= grid barrier =================
    __threadfence();
    __syncthreads();
    if (t == 0) {
        unsigned long long ticket = atomicAdd(&g_bar, 1ULL);
        unsigned long long target = (ticket >> 8) * 256ULL + 256ULL;
        volatile unsigned long long* vb = &g_bar;
        while (*vb < target) { __nanosleep(64); }
        __threadfence();
    }
    __syncthreads();

    // ================= Stage 2: attn + out epilogue =================
    float* ks = as;              // 8192
    float* qs = as + 8192;       // 256
    float* mv = as + 8448;       // 4096
    float* mf = as + 12544;      // 4096
    float* es = as + 16640;      // 4096
    float* xs = mv;              // 1024 overlay after phase B

    int b  = blk >> 5;
    int q0 = (blk & 31) * 4;

    // loads (g_q/g_k via L2 to dodge stale-L1 risk across the barrier)
    {
        const float4* gk4 = (const float4*)g_k;
        float4* ks4 = (float4*)ks;
        #pragma unroll
        for (int j = 0; j < 8; j++) {
            int idx = t + j*256;               // 2048 float4s
            ks4[idx] = __ldcg(&gk4[b*2048 + idx]);
        }
        qs[t] = __ldcg(&g_q[(b*SQ + q0 + (t>>6))*EV + (t&63)]);
        const float4* v4 = (const float4*)(value + b*SK*DIM);
        const int4*   m4 = (const int4*)  (mask  + b*SK*DIM);
        float4* mv4 = (float4*)mv;
        float4* mf4 = (float4*)mf;
        #pragma unroll
        for (int j = 0; j < 4; j++) {
            int idx = t + j*256;               // 1024 float4s
            int4 mm = m4[idx]; float4 vv = v4[idx];
            float4 av, af;
            av.x = mm.x ? vv.x : 0.f;  af.x = mm.x ? 1.f : 0.f;
            av.y = mm.y ? vv.y : 0.f;  af.y = mm.y ? 1.f : 0.f;
            av.z = mm.z ? vv.z : 0.f;  af.z = mm.z ? 1.f : 0.f;
            av.w = mm.w ? vv.w : 0.f;  af.w = mm.w ? 1.f : 0.f;
            mv4[idx] = av; mf4[idx] = af;
        }
    }
    __syncthreads();

    const float scale = 0.35355339059327373f;   // 1/sqrt(8)

    // phase A: scores + softmax weights, packed dot products.
    // vr=(q,h) 0..31, kq 0..7 (16 k each)
    {
        int vr = t >> 3;
        int q = vr >> 3, h = vr & 7;
        int kbase = (t & 7) * 16;
        float4 q0r = *(const float4*)&qs[q*EV + h*DKd];
        float4 q1r = *(const float4*)&qs[q*EV + h*DKd + 4];
        u64 qp0 = pack2(q0r.x, q0r.y);
        u64 qp1 = pack2(q0r.z, q0r.w);
        u64 qp2 = pack2(q1r.x, q1r.y);
        u64 qp3 = pack2(q1r.z, q1r.w);

        float s[16];
        #pragma unroll
        for (int i = 0; i < 16; i++) {
            const ulonglong2* kp = (const ulonglong2*)&ks[(kbase+i)*EV + h*DKd];
            ulonglong2 k0 = kp[0], k1 = kp[1];
            u64 a2 = fma2(qp0, k0.x, 0ULL);
            a2 = fma2(qp1, k0.y, a2);
            a2 = fma2(qp2, k1.x, a2);
            a2 = fma2(qp3, k1.y, a2);
            float lo, hi;
            unpack2(a2, lo, hi);
            s[i] = lo + hi;
        }
        float mx = s[0];
        #pragma unroll
        for (int i = 1; i < 16; i++) mx = fmaxf(mx, s[i]);
        mx = fmaxf(mx, __shfl_xor_sync(0xffffffff, mx, 1));
        mx = fmaxf(mx, __shfl_xor_sync(0xffffffff, mx, 2));
        mx = fmaxf(mx, __shfl_xor_sync(0xffffffff, mx, 4));
        float msc = mx * scale;
        #pragma unroll
        for (int i = 0; i < 16; i++)
            es[vr*SK + kbase + i] = __expf(fmaf(s[i], scale, -msc));
    }
    __syncthreads();

    // phase B: num/den accumulate, packed. vr 0..31, dq 0..7 (4 d each)
    // (R10 tiling: LDS.128 with 4-way lane duplication dedups to 1 wavefront)
    float4 xo;
    int vrB = t >> 3, dqB = t & 7;
    {
        u64 n01 = 0, n23 = 0, d01 = 0, d23 = 0;
        const ulonglong2* mv2 = (const ulonglong2*)mv;
        const ulonglong2* mf2 = (const ulonglong2*)mf;
        const float4* ep4 = (const float4*)&es[vrB*SK];
        #pragma unroll 4
        for (int k4 = 0; k4 < SK/4; k4++) {
            float4 e4 = ep4[k4];
            #pragma unroll
            for (int j = 0; j < 4; j++) {
                float e = (j==0) ? e4.x : (j==1) ? e4.y : (j==2) ? e4.z : e4.w;
                int k = k4*4 + j;
                u64 e2 = pack2(e, e);
                ulonglong2 v = mv2[k*8 + dqB];
                ulonglong2 m = mf2[k*8 + dqB];
                n01 = fma2(e2, v.x, n01);
                n23 = fma2(e2, v.y, n23);
                d01 = fma2(e2, m.x, d01);
                d23 = fma2(e2, m.y, d23);
            }
        }
        float n0,n1,n2,n3, dd0,dd1,dd2,dd3;
        unpack2(n01, n0, n1); unpack2(n23, n2, n3);
        unpack2(d01, dd0, dd1); unpack2(d23, dd2, dd3);
        xo.x = __fdividef(n0, dd0); xo.y = __fdividef(n1, dd1);
        xo.z = __fdividef(n2, dd2); xo.w = __fdividef(n3, dd3);
    }
    __syncthreads();    // mv/mf reads done; safe to overlay xs
    {
        int q = vrB >> 3, h = vrB & 7;
        *(float4*)&xs[q*256 + h*DIM + dqB*4] = xo;
    }
    __syncthreads();

    // epilogue: y[q][c] = sum_p xs[q][p] * wo[p][c] + bo[c]
    // thread = (col pair cp, row qsel). 4 independent packed chains over
    // p-chunks of 64 -> serial-FMA floor 256 cyc (was 1024), ~32 LDGs in
    // flight to cover L2 latency.
    {
        int cp   = (t & 63) * 2;
        int qsel = t >> 6;            // 0..3
        const float* xp = &xs[qsel*256];
        u64 a0 = 0, a1 = 0, a2 = 0, a3 = 0;
        #pragma unroll 8
        for (int p = 0; p < 64; p++) {
            u64 x0 = pack2(xp[p],       xp[p]);
            u64 x1 = pack2(xp[p + 64],  xp[p + 64]);
            u64 x2 = pack2(xp[p + 128], xp[p + 128]);
            u64 x3 = pack2(xp[p + 192], xp[p + 192]);
            a0 = fma2(x0, *(const u64*)&wo[(p      )*NH + cp], a0);
            a1 = fma2(x1, *(const u64*)&wo[(p +  64)*NH + cp], a1);
            a2 = fma2(x2, *(const u64*)&wo[(p + 128)*NH + cp], a2);
            a3 = fma2(x3, *(const u64*)&wo[(p + 192)*NH + cp], a3);
        }
        u64 s = add2(add2(a0, a1), add2(a2, a3));
        s = add2(s, pack2(bo[cp], bo[cp+1]));
        float r0v, r1v;
        unpack2(s, r0v, r1v);
        float2 o; o.x = r0v; o.y = r1v;
        *(float2*)&y_out[(b*SQ + q0 + qsel)*NH + cp] = o;
    }
}

// ---------------------------------------------------------------------------
extern "C" void kernel_launch(void* const* d_in, const int* in_sizes, int n_in,
                              void* d_out, int out_size)
{
    bool dictOrder = (in_sizes[4] == Bn*SK*DIM);

    const float *qv, *kv, *val, *imp, *w1, *b1, *w2, *wq, *bq, *wk, *bk,
                *wo, *bo, *wd1, *bd1, *lng, *lnb, *wd2, *bd2;
    const int* mask;

    if (dictOrder) {
        qv  = (const float*)d_in[0];  kv  = (const float*)d_in[1];
        val = (const float*)d_in[2];  imp = (const float*)d_in[3];
        mask= (const int*)  d_in[4];
        w1  = (const float*)d_in[5];  b1  = (const float*)d_in[6];
        w2  = (const float*)d_in[7];
        wq  = (const float*)d_in[8];  bq  = (const float*)d_in[9];
        wk  = (const float*)d_in[10]; bk  = (const float*)d_in[11];
        wo  = (const float*)d_in[12]; bo  = (const float*)d_in[13];
        wd1 = (const float*)d_in[14]; bd1 = (const float*)d_in[15];
        lng = (const float*)d_in[16]; lnb = (const float*)d_in[17];
        wd2 = (const float*)d_in[18]; bd2 = (const float*)d_in[19];
    } else {
        qv  = (const float*)d_in[0];  kv  = (const float*)d_in[1];
        val = (const float*)d_in[2];  imp = (const float*)d_in[3];
        w1  = (const float*)d_in[4];  b1  = (const float*)d_in[5];
        w2  = (const float*)d_in[6];
        wq  = (const float*)d_in[7];  bq  = (const float*)d_in[8];
        wk  = (const float*)d_in[9];  bk  = (const float*)d_in[10];
        wo  = (const float*)d_in[11]; bo  = (const float*)d_in[12];
        wd1 = (const float*)d_in[13]; bd1 = (const float*)d_in[14];
        lng = (const float*)d_in[15]; lnb = (const float*)d_in[16];
        wd2 = (const float*)d_in[17]; bd2 = (const float*)d_in[18];
        mask= (const int*)  d_in[19];
    }

    float* y  = (float*)d_out;                       // [8,128,128]
    float* qd = (float*)d_out + Bn*SQ*NH;            // [8,128,128]

    cudaFuncSetAttribute(mega_kernel,
                         cudaFuncAttributeMaxDynamicSharedMemorySize,
                         20736 * sizeof(float));

    mega_kernel<<<256, 256, 20736 * sizeof(float)>>>(
        qv, kv, val, mask, w1, b1, w2, wq, bq, wk, bk, wo, bo,
        imp, wd1, bd1, lng, lnb, wd2, bd2, y, qd);
}

// round 13
// speedup vs baseline: 1.3643x; 1.0921x over previous
#include <cuda_runtime.h>
#include <math.h>
#include <stdint.h>

#define Bn  8
#define SQ  128
#define SK  128
#define IVD 32
#define DIM 32
#define EV  64
#define Hh  8
#define NH  128
#define DKd 8

typedef unsigned long long u64;

// scratch (allocation-free rule: device globals)
__device__ float g_q[Bn*SQ*EV];
__device__ float g_k[Bn*SK*EV];
__device__ unsigned long long g_bar = 0;   // monotonic ticket barrier

__device__ __forceinline__ void cp_async16(uint32_t saddr, const void* gaddr) {
    asm volatile("cp.async.cg.shared.global [%0], [%1], 16;\n"
                 :: "r"(saddr), "l"(gaddr));
}
__device__ __forceinline__ void cp_commit() {
    asm volatile("cp.async.commit_group;\n");
}
__device__ __forceinline__ void cp_wait0() {
    asm volatile("cp.async.wait_group 0;\n");
}

__device__ __forceinline__ float fast_tanh(float x) {
    x = fminf(fmaxf(x, -15.f), 15.f);
    float e = __expf(2.f * x);
    return __fdividef(e - 1.f, e + 1.f);
}

// ---- packed fp32x2 (Blackwell FFMA2; per-lane IEEE fp32) ----
__device__ __forceinline__ u64 pack2(float lo, float hi) {
    u64 r; asm("mov.b64 %0, {%1, %2};" : "=l"(r) : "f"(lo), "f"(hi)); return r;
}
__device__ __forceinline__ void unpack2(u64 v, float& lo, float& hi) {
    asm("mov.b64 {%0, %1}, %2;" : "=f"(lo), "=f"(hi) : "l"(v));
}
__device__ __forceinline__ u64 fma2(u64 a, u64 b, u64 c) {
    u64 d; asm("fma.rn.f32x2 %0, %1, %2, %3;"
               : "=l"(d) : "l"(a), "l"(b), "l"(c)); return d;
}

// ---------------------------------------------------------------------------
// Single fused kernel. 256 blocks x 256 threads, 81KB dyn smem (2 blocks/SM
// capacity -> all 256 co-resident -> grid barrier deadlock-free).
//   Stage 1: blocks [0,128)   : proj, 16 rows/block (smem floats 0..11776)
//            blocks [128,256) : impute MLP, 8 rows/block (floats 0..1216)
//   Pre-barrier: ALL blocks also load+convert value/mask -> mv/mf
//                (floats 12544..20736, disjoint from stage-1 workspace) so
//                that LDG latency hides under stage-1 tail + barrier skew.
//   grid barrier
//   Stage 2: attn block=(b, 4q, 8 heads) + fused out-GEMM epilogue.
// smem map stage 2: ks 0..8192 | qs 8192..8448 | es 8448..12544 |
//                   mv 12544..16640 | mf 16640..20736 | xs overlays ks.
// ---------------------------------------------------------------------------
extern __shared__ float as[];
__global__ void __launch_bounds__(256) mega_kernel(
    const float* __restrict__ qv, const float* __restrict__ kv,
    const float* __restrict__ value, const int* __restrict__ mask,
    const float* __restrict__ w1, const float* __restrict__ b1,
    const float* __restrict__ w2,
    const float* __restrict__ wq, const float* __restrict__ bq,
    const float* __restrict__ wk, const float* __restrict__ bk,
    const float* __restrict__ wo, const float* __restrict__ bo,
    const float* __restrict__ imp,
    const float* __restrict__ wd1, const float* __restrict__ bd1,
    const float* __restrict__ lng, const float* __restrict__ lnb,
    const float* __restrict__ wd2, const float* __restrict__ bd2,
    float* __restrict__ y_out, float* __restrict__ qd_out)
{
    int t   = threadIdx.x;
    int blk = blockIdx.x;

    int b  = blk >> 5;
    int q0 = (blk & 31) * 4;

    float* ks = as;              // 8192  (stage 2)
    float* qs = as + 8192;       // 256
    float* es = as + 8448;       // 4096
    float* mv = as + 12544;      // 4096  (loaded pre-barrier)
    float* mf = as + 16640;      // 4096
    float* xs = as;              // 1024 overlay on ks after phase A

    if (blk < 128) {
        // ========== Stage 1a: proj, 16 rows/block ==========
        float* xs_t = as;            // [i][r] 32x16 transposed, 512 f
        float* ht   = as + 512;      // [p][r] 128x16 transposed, 2048 f
        float* et   = as + 2560;     // [p][r] 64x16 transposed, 1024 f
        float* ws2  = as + 3584;     // 8192 f (ends at 11776 < 12544)

        int r0 = blk * 16;                     // row in [0,2048)
        bool isQ = r0 < Bn*SQ;
        int rr0 = isQ ? r0 : r0 - Bn*SQ;
        const float* xin = isQ ? qv : kv;
        const float* wp  = isQ ? wq : wk;
        const float* bp  = isQ ? bq : bk;
        float* outp      = isQ ? g_q : g_k;

        // stage w2 (latency hidden by phase 1)
        {
            uint32_t sb = (uint32_t)__cvta_generic_to_shared(ws2);
            #pragma unroll
            for (int j = 0; j < 8; j++) {
                int idx = t + j*256;           // 2048 float4s
                cp_async16(sb + idx*16, w2 + idx*4);
            }
            cp_commit();
        }

        // load 16 input rows, transposed [i][r]
        #pragma unroll
        for (int j = 0; j < 2; j++) {
            int idx = t + j*256;               // 0..511
            int r = idx >> 5, i = idx & 31;
            xs_t[i*16 + r] = xin[rr0*IVD + idx];
        }
        __syncthreads();

        // phase 1: hidden. thread = (col c1 of 128, 8 rows), packed pairs
        {
            int c1  = t & 127;
            int rh1 = (t >> 7) * 8;
            float bb = b1[c1];
            u64 bb2 = pack2(bb, bb);
            u64 a01 = bb2, a23 = bb2, a45 = bb2, a67 = bb2;
            #pragma unroll
            for (int i = 0; i < IVD; i++) {
                float w = w1[i*NH + c1];
                u64 w2p = pack2(w, w);
                ulonglong2 x0 = *(const ulonglong2*)&xs_t[i*16 + rh1];
                ulonglong2 x1 = *(const ulonglong2*)&xs_t[i*16 + rh1 + 4];
                a01 = fma2(x0.x, w2p, a01);
                a23 = fma2(x0.y, w2p, a23);
                a45 = fma2(x1.x, w2p, a45);
                a67 = fma2(x1.y, w2p, a67);
            }
            float v0,v1,v2,v3,v4,v5,v6,v7;
            unpack2(a01, v0, v1); unpack2(a23, v2, v3);
            unpack2(a45, v4, v5); unpack2(a67, v6, v7);
            float4 h0, h1;
            h0.x = fast_tanh(v0); h0.y = fast_tanh(v1);
            h0.z = fast_tanh(v2); h0.w = fast_tanh(v3);
            h1.x = fast_tanh(v4); h1.y = fast_tanh(v5);
            h1.z = fast_tanh(v6); h1.w = fast_tanh(v7);
            *(float4*)&ht[c1*16 + rh1]     = h0;
            *(float4*)&ht[c1*16 + rh1 + 4] = h1;
        }
        cp_wait0();
        __syncthreads();

        int c  = t & 63;
        int rg = (t >> 6) * 4;        // rows rg..rg+3

        // phase 2: embed (all-smem), packed
        {
            u64 a01 = 0, a23 = 0;
            #pragma unroll 8
            for (int p = 0; p < NH; p++) {
                float w = ws2[p*EV + c];
                u64 w2p = pack2(w, w);
                ulonglong2 h = *(const ulonglong2*)&ht[p*16 + rg];
                a01 = fma2(h.x, w2p, a01);
                a23 = fma2(h.y, w2p, a23);
            }
            float o0,o1,o2,o3;
            unpack2(a01, o0, o1); unpack2(a23, o2, o3);
            float4 o; o.x=o0; o.y=o1; o.z=o2; o.w=o3;
            *(float4*)&et[c*16 + rg] = o;
        }
        __syncthreads();

        // phase 3: q/k projection, packed
        {
            float bb = bp[c];
            u64 bb2 = pack2(bb, bb);
            u64 a01 = bb2, a23 = bb2;
            #pragma unroll 8
            for (int p = 0; p < EV; p++) {
                float w = wp[p*EV + c];
                u64 w2p = pack2(w, w);
                ulonglong2 e = *(const ulonglong2*)&et[p*16 + rg];
                a01 = fma2(e.x, w2p, a01);
                a23 = fma2(e.y, w2p, a23);
            }
            float o0,o1,o2,o3;
            unpack2(a01, o0, o1); unpack2(a23, o2, o3);
            outp[(rr0+rg+0)*EV + c] = o0;
            outp[(rr0+rg+1)*EV + c] = o1;
            outp[(rr0+rg+2)*EV + c] = o2;
            outp[(rr0+rg+3)*EV + c] = o3;
        }
    } else {
        // ========== Stage 1b: impute MLP, 8 rows/block ==========
        float* xi   = as;            // [8][16] 128 f
        float* htm  = as + 128;      // [128][8] transposed, 1024 f
        float* redS = as + 1152;     // 32 f
        float* redQ = as + 1184;     // 32 f

        int row0 = (blk - 128) * 8;
        if (t < 128) xi[t] = imp[row0*16 + t];
        __syncthreads();

        int c1   = t & 127;
        int base = (t >> 7) * 4;     // rows base..base+3
        int w8   = t >> 5;
        int lane = t & 31;

        float a[4];
        {
            float bb = bd1[c1];
            #pragma unroll
            for (int j = 0; j < 4; j++) a[j] = bb;
            #pragma unroll
            for (int i = 0; i < 16; i++) {
                float w = wd1[i*NH + c1];
                #pragma unroll
                for (int j = 0; j < 4; j++)
                    a[j] = fmaf(xi[(base+j)*16 + i], w, a[j]);
            }
        }
        float ss[4], qq[4];
        #pragma unroll
        for (int j = 0; j < 4; j++) { ss[j] = a[j]; qq[j] = a[j]*a[j]; }
        #pragma unroll
        for (int off = 16; off > 0; off >>= 1) {
            #pragma unroll
            for (int j = 0; j < 4; j++) {
                ss[j] += __shfl_xor_sync(0xffffffff, ss[j], off);
                qq[j] += __shfl_xor_sync(0xffffffff, qq[j], off);
            }
        }
        if (lane == 0) {
            #pragma unroll
            for (int j = 0; j < 4; j++) { redS[w8*4+j] = ss[j]; redQ[w8*4+j] = qq[j]; }
        }
        __syncthreads();

        float g = lng[c1], be = lnb[c1];
        int gw = (base == 0) ? 0 : 4;
        {
            float4 hv; float* hp = (float*)&hv;
            #pragma unroll
            for (int j = 0; j < 4; j++) {
                float S = redS[(gw+0)*4+j] + redS[(gw+1)*4+j]
                        + redS[(gw+2)*4+j] + redS[(gw+3)*4+j];
                float Q = redQ[(gw+0)*4+j] + redQ[(gw+1)*4+j]
                        + redQ[(gw+2)*4+j] + redQ[(gw+3)*4+j];
                float mu  = S * (1.f/128.f);
                float var = Q * (1.f/128.f) - mu*mu;
                float ln = (a[j] - mu) * rsqrtf(var + 1e-5f) * g + be;
                hp[j] = fmaxf(ln, 0.f);
            }
            *(float4*)&htm[c1*8 + base] = hv;
        }
        __syncthreads();

        // GEMM2, packed row pairs
        {
            float bb = bd2[c1];
            u64 bb2 = pack2(bb, bb);
            u64 a01 = bb2, a23 = bb2;
            #pragma unroll 8
            for (int p = 0; p < NH; p++) {
                float w = wd2[p*NH + c1];
                u64 w2p = pack2(w, w);
                ulonglong2 h = *(const ulonglong2*)&htm[p*8 + base];
                a01 = fma2(h.x, w2p, a01);
                a23 = fma2(h.y, w2p, a23);
            }
            float o0,o1,o2,o3;
            unpack2(a01, o0, o1); unpack2(a23, o2, o3);
            qd_out[(row0+base+0)*NH + c1] = o0;
            qd_out[(row0+base+1)*NH + c1] = o1;
            qd_out[(row0+base+2)*NH + c1] = o2;
            qd_out[(row0+base+3)*NH + c1] = o3;
        }
    }

    // ===== pre-barrier: load + convert value/mask -> mv/mf (independent
    // of proj; LDG latency hides under stage-1 tail + barrier skew) =====
    __syncthreads();     // stage-1 smem reads done before any mv/mf reuse
    {
        const float4* v4 = (const float4*)(value + b*SK*DIM);
        const int4*   m4 = (const int4*)  (mask  + b*SK*DIM);
        float4* mv4 = (float4*)mv;
        float4* mf4 = (float4*)mf;
        #pragma unroll
        for (int j = 0; j < 4; j++) {
            int idx = t + j*256;               // 1024 float4s
            int4 mm = m4[idx]; float4 vv = v4[idx];
            float4 av, af;
            av.x = mm.x ? vv.x : 0.f;  af.x = mm.x ? 1.f : 0.f;
            av.y = mm.y ? vv.y : 0.f;  af.y = mm.y ? 1.f : 0.f;
            av.z = mm.z ? vv.z : 0.f;  af.z = mm.z ? 1.f : 0.f;
            av.w = mm.w ? vv.w : 0.f;  af.w = mm.w ? 1.f : 0.f;
            mv4[idx] = av; mf4[idx] = af;
        }
    }

    // ================= grid barrier =================
    __threadfence();
    __syncthreads();
    if (t == 0) {
        unsigned long long ticket = atomicAdd(&g_bar, 1ULL);
        unsigned long long target = (ticket >> 8) * 256ULL + 256ULL;
        volatile unsigned long long* vb = &g_bar;
        while (*vb < target) { __nanosleep(64); }
        __threadfence();
    }
    __syncthreads();

    // ================= Stage 2: attn + out epilogue =================
    // load ks/qs (proj-dependent; via L2 to dodge stale-L1 across barrier)
    {
        const float4* gk4 = (const float4*)g_k;
        float4* ks4 = (float4*)ks;
        #pragma unroll
        for (int j = 0; j < 8; j++) {
            int idx = t + j*256;               // 2048 float4s
            ks4[idx] = __ldcg(&gk4[b*2048 + idx]);
        }
        qs[t] = __ldcg(&g_q[(b*SQ + q0 + (t>>6))*EV + (t&63)]);
    }
    __syncthreads();

    const float scale = 0.35355339059327373f;   // 1/sqrt(8)

    // phase A: scores + softmax weights, packed dot products.
    // vr=(q,h) 0..31, kq 0..7 (16 k each)
    {
        int vr = t >> 3;
        int q = vr >> 3, h = vr & 7;
        int kbase = (t & 7) * 16;
        float4 q0r = *(const float4*)&qs[q*EV + h*DKd];
        float4 q1r = *(const float4*)&qs[q*EV + h*DKd + 4];
        u64 qp0 = pack2(q0r.x, q0r.y);
        u64 qp1 = pack2(q0r.z, q0r.w);
        u64 qp2 = pack2(q1r.x, q1r.y);
        u64 qp3 = pack2(q1r.z, q1r.w);

        float s[16];
        #pragma unroll
        for (int i = 0; i < 16; i++) {
            const ulonglong2* kp = (const ulonglong2*)&ks[(kbase+i)*EV + h*DKd];
            ulonglong2 k0 = kp[0], k1 = kp[1];
            u64 a2 = fma2(qp0, k0.x, 0ULL);
            a2 = fma2(qp1, k0.y, a2);
            a2 = fma2(qp2, k1.x, a2);
            a2 = fma2(qp3, k1.y, a2);
            float lo, hi;
            unpack2(a2, lo, hi);
            s[i] = lo + hi;
        }
        float mx = s[0];
        #pragma unroll
        for (int i = 1; i < 16; i++) mx = fmaxf(mx, s[i]);
        mx = fmaxf(mx, __shfl_xor_sync(0xffffffff, mx, 1));
        mx = fmaxf(mx, __shfl_xor_sync(0xffffffff, mx, 2));
        mx = fmaxf(mx, __shfl_xor_sync(0xffffffff, mx, 4));
        float msc = mx * scale;
        #pragma unroll
        for (int i = 0; i < 16; i++)
            es[vr*SK + kbase + i] = __expf(fmaf(s[i], scale, -msc));
    }
    __syncthreads();   // ks reads done -> xs overlay (on ks) is safe below

    // phase B: num/den accumulate, packed. vr 0..31, dq 0..7 (4 d each)
    float4 xo;
    int vrB = t >> 3, dqB = t & 7;
    {
        u64 n01 = 0, n23 = 0, d01 = 0, d23 = 0;
        const ulonglong2* mv2 = (const ulonglong2*)mv;
        const ulonglong2* mf2 = (const ulonglong2*)mf;
        const float4* ep4 = (const float4*)&es[vrB*SK];
        #pragma unroll 4
        for (int k4 = 0; k4 < SK/4; k4++) {
            float4 e4 = ep4[k4];
            #pragma unroll
            for (int j = 0; j < 4; j++) {
                float e = (j==0) ? e4.x : (j==1) ? e4.y : (j==2) ? e4.z : e4.w;
                int k = k4*4 + j;
                u64 e2 = pack2(e, e);
                ulonglong2 v = mv2[k*8 + dqB];
                ulonglong2 m = mf2[k*8 + dqB];
                n01 = fma2(e2, v.x, n01);
                n23 = fma2(e2, v.y, n23);
                d01 = fma2(e2, m.x, d01);
                d23 = fma2(e2, m.y, d23);
            }
        }
        float n0,n1,n2,n3, dd0,dd1,dd2,dd3;
        unpack2(n01, n0, n1); unpack2(n23, n2, n3);
        unpack2(d01, dd0, dd1); unpack2(d23, dd2, dd3);
        xo.x = __fdividef(n0, dd0); xo.y = __fdividef(n1, dd1);
        xo.z = __fdividef(n2, dd2); xo.w = __fdividef(n3, dd3);
    }
    {
        int q = vrB >> 3, h = vrB & 7;
        *(float4*)&xs[q*256 + h*DIM + dqB*4] = xo;
    }
    __syncthreads();

    // epilogue: y[q][c] = sum_p xs[q][p] * wo[p][c] + bo[c]
    // thread = (col pair cp, row qsel); packed col-pair FMA, LDG.64 wo.
    {
        int cp   = (t & 63) * 2;
        int qsel = t >> 6;            // 0..3
        u64 acc = pack2(bo[cp], bo[cp+1]);
        const float* xp = &xs[qsel*256];
        #pragma unroll 8
        for (int p = 0; p < 256; p++) {
            u64 w2p = *(const u64*)&wo[p*NH + cp];
            u64 x2  = pack2(xp[p], xp[p]);
            acc = fma2(x2, w2p, acc);
        }
        float r0v, r1v;
        unpack2(acc, r0v, r1v);
        float2 o; o.x = r0v; o.y = r1v;
        *(float2*)&y_out[(b*SQ + q0 + qsel)*NH + cp] = o;
    }
}

// ---------------------------------------------------------------------------
extern "C" void kernel_launch(void* const* d_in, const int* in_sizes, int n_in,
                              void* d_out, int out_size)
{
    bool dictOrder = (in_sizes[4] == Bn*SK*DIM);

    const float *qv, *kv, *val, *imp, *w1, *b1, *w2, *wq, *bq, *wk, *bk,
                *wo, *bo, *wd1, *bd1, *lng, *lnb, *wd2, *bd2;
    const int* mask;

    if (dictOrder) {
        qv  = (const float*)d_in[0];  kv  = (const float*)d_in[1];
        val = (const float*)d_in[2];  imp = (const float*)d_in[3];
        mask= (const int*)  d_in[4];
        w1  = (const float*)d_in[5];  b1  = (const float*)d_in[6];
        w2  = (const float*)d_in[7];
        wq  = (const float*)d_in[8];  bq  = (const float*)d_in[9];
        wk  = (const float*)d_in[10]; bk  = (const float*)d_in[11];
        wo  = (const float*)d_in[12]; bo  = (const float*)d_in[13];
        wd1 = (const float*)d_in[14]; bd1 = (const float*)d_in[15];
        lng = (const float*)d_in[16]; lnb = (const float*)d_in[17];
        wd2 = (const float*)d_in[18]; bd2 = (const float*)d_in[19];
    } else {
        qv  = (const float*)d_in[0];  kv  = (const float*)d_in[1];
        val = (const float*)d_in[2];  imp = (const float*)d_in[3];
        w1  = (const float*)d_in[4];  b1  = (const float*)d_in[5];
        w2  = (const float*)d_in[6];
        wq  = (const float*)d_in[7];  bq  = (const float*)d_in[8];
        wk  = (const float*)d_in[9];  bk  = (const float*)d_in[10];
        wo  = (const float*)d_in[11]; bo  = (const float*)d_in[12];
        wd1 = (const float*)d_in[13]; bd1 = (const float*)d_in[14];
        lng = (const float*)d_in[15]; lnb = (const float*)d_in[16];
        wd2 = (const float*)d_in[17]; bd2 = (const float*)d_in[18];
        mask= (const int*)  d_in[19];
    }

    float* y  = (float*)d_out;                       // [8,128,128]
    float* qd = (float*)d_out + Bn*SQ*NH;            // [8,128,128]

    cudaFuncSetAttribute(mega_kernel,
                         cudaFuncAttributeMaxDynamicSharedMemorySize,
                         20736 * sizeof(float));

    mega_kernel<<<256, 256, 20736 * sizeof(float)>>>(
        qv, kv, val, mask, w1, b1, w2, wq, bq, wk, bk, wo, bo,
        imp, wd1, bd1, lng, lnb, wd2, bd2, y, qd);
}

// round 14
// speedup vs baseline: 1.3732x; 1.0065x over previous
#include <cuda_runtime.h>
#include <math.h>
#include <stdint.h>

#define Bn  8
#define SQ  128
#define SK  128
#define IVD 32
#define DIM 32
#define EV  64
#define Hh  8
#define NH  128
#define DKd 8

#define ESS 136   // es row stride (conflict-breaking pad)
#define HTS 20    // ht/et row stride (conflict-breaking pad)

typedef unsigned long long u64;

// scratch (allocation-free rule: device globals)
__device__ float g_q[Bn*SQ*EV];
__device__ float g_k[Bn*SK*EV];
__device__ unsigned long long g_bar = 0;   // monotonic ticket barrier

__device__ __forceinline__ void cp_async16(uint32_t saddr, const void* gaddr) {
    asm volatile("cp.async.cg.shared.global [%0], [%1], 16;\n"
                 :: "r"(saddr), "l"(gaddr));
}
__device__ __forceinline__ void cp_commit() {
    asm volatile("cp.async.commit_group;\n");
}
__device__ __forceinline__ void cp_wait0() {
    asm volatile("cp.async.wait_group 0;\n");
}

__device__ __forceinline__ float fast_tanh(float x) {
    x = fminf(fmaxf(x, -15.f), 15.f);
    float e = __expf(2.f * x);
    return __fdividef(e - 1.f, e + 1.f);
}

// ---- packed fp32x2 (Blackwell FFMA2; per-lane IEEE fp32) ----
__device__ __forceinline__ u64 pack2(float lo, float hi) {
    u64 r; asm("mov.b64 %0, {%1, %2};" : "=l"(r) : "f"(lo), "f"(hi)); return r;
}
__device__ __forceinline__ void unpack2(u64 v, float& lo, float& hi) {
    asm("mov.b64 {%0, %1}, %2;" : "=f"(lo), "=f"(hi) : "l"(v));
}
__device__ __forceinline__ u64 fma2(u64 a, u64 b, u64 c) {
    u64 d; asm("fma.rn.f32x2 %0, %1, %2, %3;"
               : "=l"(d) : "l"(a), "l"(b), "l"(c)); return d;
}

// ---------------------------------------------------------------------------
// Single fused kernel. 256 blocks x 256 threads, 84KB dyn smem (2 blocks/SM
// capacity -> all 256 co-resident -> grid barrier deadlock-free).
//   Stage 1: blocks [0,128)   : proj, 16 rows/block (smem floats 0..12544)
//            blocks [128,256) : impute MLP, 8 rows/block
//   Pre-barrier: ALL blocks load+convert value/mask -> mv/mf (12800..20992)
//   grid barrier
//   Stage 2: attn block=(b, 4q, 8 heads) + fused out-GEMM epilogue.
// Bank-conflict fixes: es stride 136 + float4 stores; phase A warp-per-head
// read mapping; ht/et stride 20.
// smem map stage 2: ks 0..8192 | qs 8192..8448 | es 8448..12800 |
//                   mv 12800..16896 | mf 16896..20992 | xs overlays ks.
// ---------------------------------------------------------------------------
extern __shared__ float as[];
__global__ void __launch_bounds__(256) mega_kernel(
    const float* __restrict__ qv, const float* __restrict__ kv,
    const float* __restrict__ value, const int* __restrict__ mask,
    const float* __restrict__ w1, const float* __restrict__ b1,
    const float* __restrict__ w2,
    const float* __restrict__ wq, const float* __restrict__ bq,
    const float* __restrict__ wk, const float* __restrict__ bk,
    const float* __restrict__ wo, const float* __restrict__ bo,
    const float* __restrict__ imp,
    const float* __restrict__ wd1, const float* __restrict__ bd1,
    const float* __restrict__ lng, const float* __restrict__ lnb,
    const float* __restrict__ wd2, const float* __restrict__ bd2,
    float* __restrict__ y_out, float* __restrict__ qd_out)
{
    int t   = threadIdx.x;
    int blk = blockIdx.x;

    int b  = blk >> 5;
    int q0 = (blk & 31) * 4;

    float* ks = as;              // 8192  (stage 2)
    float* qs = as + 8192;       // 256
    float* es = as + 8448;       // 4352 (32 rows x ESS)
    float* mv = as + 12800;      // 4096  (loaded pre-barrier)
    float* mf = as + 16896;      // 4096
    float* xs = as;              // 1024 overlay on ks after phase A

    if (blk < 128) {
        // ========== Stage 1a: proj, 16 rows/block ==========
        float* xs_t = as;            // [i][r] 32x16 transposed, 512 f
        float* ht   = as + 512;      // [p][r] 128xHTS transposed, 2560 f
        float* et   = as + 3072;     // [p][r] 64xHTS transposed, 1280 f
        float* ws2  = as + 4352;     // 8192 f (ends at 12544 < 12800)

        int r0 = blk * 16;                     // row in [0,2048)
        bool isQ = r0 < Bn*SQ;
        int rr0 = isQ ? r0 : r0 - Bn*SQ;
        const float* xin = isQ ? qv : kv;
        const float* wp  = isQ ? wq : wk;
        const float* bp  = isQ ? bq : bk;
        float* outp      = isQ ? g_q : g_k;

        // stage w2 (latency hidden by phase 1)
        {
            uint32_t sb = (uint32_t)__cvta_generic_to_shared(ws2);
            #pragma unroll
            for (int j = 0; j < 8; j++) {
                int idx = t + j*256;           // 2048 float4s
                cp_async16(sb + idx*16, w2 + idx*4);
            }
            cp_commit();
        }

        // load 16 input rows, transposed [i][r]
        #pragma unroll
        for (int j = 0; j < 2; j++) {
            int idx = t + j*256;               // 0..511
            int r = idx >> 5, i = idx & 31;
            xs_t[i*16 + r] = xin[rr0*IVD + idx];
        }
        __syncthreads();

        // phase 1: hidden. thread = (col c1 of 128, 8 rows), packed pairs
        {
            int c1  = t & 127;
            int rh1 = (t >> 7) * 8;
            float bb = b1[c1];
            u64 bb2 = pack2(bb, bb);
            u64 a01 = bb2, a23 = bb2, a45 = bb2, a67 = bb2;
            #pragma unroll
            for (int i = 0; i < IVD; i++) {
                float w = w1[i*NH + c1];
                u64 w2p = pack2(w, w);
                ulonglong2 x0 = *(const ulonglong2*)&xs_t[i*16 + rh1];
                ulonglong2 x1 = *(const ulonglong2*)&xs_t[i*16 + rh1 + 4];
                a01 = fma2(x0.x, w2p, a01);
                a23 = fma2(x0.y, w2p, a23);
                a45 = fma2(x1.x, w2p, a45);
                a67 = fma2(x1.y, w2p, a67);
            }
            float v0,v1,v2,v3,v4,v5,v6,v7;
            unpack2(a01, v0, v1); unpack2(a23, v2, v3);
            unpack2(a45, v4, v5); unpack2(a67, v6, v7);
            float4 h0, h1;
            h0.x = fast_tanh(v0); h0.y = fast_tanh(v1);
            h0.z = fast_tanh(v2); h0.w = fast_tanh(v3);
            h1.x = fast_tanh(v4); h1.y = fast_tanh(v5);
            h1.z = fast_tanh(v6); h1.w = fast_tanh(v7);
            *(float4*)&ht[c1*HTS + rh1]     = h0;   // stride 20: conflict-free
            *(float4*)&ht[c1*HTS + rh1 + 4] = h1;
        }
        cp_wait0();
        __syncthreads();

        int c  = t & 63;
        int rg = (t >> 6) * 4;        // rows rg..rg+3

        // phase 2: embed (all-smem), packed
        {
            u64 a01 = 0, a23 = 0;
            #pragma unroll 8
            for (int p = 0; p < NH; p++) {
                float w = ws2[p*EV + c];
                u64 w2p = pack2(w, w);
                ulonglong2 h = *(const ulonglong2*)&ht[p*HTS + rg];
                a01 = fma2(h.x, w2p, a01);
                a23 = fma2(h.y, w2p, a23);
            }
            float o0,o1,o2,o3;
            unpack2(a01, o0, o1); unpack2(a23, o2, o3);
            float4 o; o.x=o0; o.y=o1; o.z=o2; o.w=o3;
            *(float4*)&et[c*HTS + rg] = o;
        }
        __syncthreads();

        // phase 3: q/k projection, packed
        {
            float bb = bp[c];
            u64 bb2 = pack2(bb, bb);
            u64 a01 = bb2, a23 = bb2;
            #pragma unroll 8
            for (int p = 0; p < EV; p++) {
                float w = wp[p*EV + c];
                u64 w2p = pack2(w, w);
                ulonglong2 e = *(const ulonglong2*)&et[p*HTS + rg];
                a01 = fma2(e.x, w2p, a01);
                a23 = fma2(e.y, w2p, a23);
            }
            float o0,o1,o2,o3;
            unpack2(a01, o0, o1); unpack2(a23, o2, o3);
            outp[(rr0+rg+0)*EV + c] = o0;
            outp[(rr0+rg+1)*EV + c] = o1;
            outp[(rr0+rg+2)*EV + c] = o2;
            outp[(rr0+rg+3)*EV + c] = o3;
        }
    } else {
        // ========== Stage 1b: impute MLP, 8 rows/block ==========
        float* xi   = as;            // [8][16] 128 f
        float* htm  = as + 128;      // [128][8] transposed, 1024 f
        float* redS = as + 1152;     // 32 f
        float* redQ = as + 1184;     // 32 f

        int row0 = (blk - 128) * 8;
        if (t < 128) xi[t] = imp[row0*16 + t];
        __syncthreads();

        int c1   = t & 127;
        int base = (t >> 7) * 4;     // rows base..base+3
        int w8   = t >> 5;
        int lane = t & 31;

        float a[4];
        {
            float bb = bd1[c1];
            #pragma unroll
            for (int j = 0; j < 4; j++) a[j] = bb;
            #pragma unroll
            for (int i = 0; i < 16; i++) {
                float w = wd1[i*NH + c1];
                #pragma unroll
                for (int j = 0; j < 4; j++)
                    a[j] = fmaf(xi[(base+j)*16 + i], w, a[j]);
            }
        }
        float ss[4], qq[4];
        #pragma unroll
        for (int j = 0; j < 4; j++) { ss[j] = a[j]; qq[j] = a[j]*a[j]; }
        #pragma unroll
        for (int off = 16; off > 0; off >>= 1) {
            #pragma unroll
            for (int j = 0; j < 4; j++) {
                ss[j] += __shfl_xor_sync(0xffffffff, ss[j], off);
                qq[j] += __shfl_xor_sync(0xffffffff, qq[j], off);
            }
        }
        if (lane == 0) {
            #pragma unroll
            for (int j = 0; j < 4; j++) { redS[w8*4+j] = ss[j]; redQ[w8*4+j] = qq[j]; }
        }
        __syncthreads();

        float g = lng[c1], be = lnb[c1];
        int gw = (base == 0) ? 0 : 4;
        {
            float4 hv; float* hp = (float*)&hv;
            #pragma unroll
            for (int j = 0; j < 4; j++) {
                float S = redS[(gw+0)*4+j] + redS[(gw+1)*4+j]
                        + redS[(gw+2)*4+j] + redS[(gw+3)*4+j];
                float Q = redQ[(gw+0)*4+j] + redQ[(gw+1)*4+j]
                        + redQ[(gw+2)*4+j] + redQ[(gw+3)*4+j];
                float mu  = S * (1.f/128.f);
                float var = Q * (1.f/128.f) - mu*mu;
                float ln = (a[j] - mu) * rsqrtf(var + 1e-5f) * g + be;
                hp[j] = fmaxf(ln, 0.f);
            }
            *(float4*)&htm[c1*8 + base] = hv;
        }
        __syncthreads();

        // GEMM2, packed row pairs
        {
            float bb = bd2[c1];
            u64 bb2 = pack2(bb, bb);
            u64 a01 = bb2, a23 = bb2;
            #pragma unroll 8
            for (int p = 0; p < NH; p++) {
                float w = wd2[p*NH + c1];
                u64 w2p = pack2(w, w);
                ulonglong2 h = *(const ulonglong2*)&htm[p*8 + base];
                a01 = fma2(h.x, w2p, a01);
                a23 = fma2(h.y, w2p, a23);
            }
            float o0,o1,o2,o3;
            unpack2(a01, o0, o1); unpack2(a23, o2, o3);
            qd_out[(row0+base+0)*NH + c1] = o0;
            qd_out[(row0+base+1)*NH + c1] = o1;
            qd_out[(row0+base+2)*NH + c1] = o2;
            qd_out[(row0+base+3)*NH + c1] = o3;
        }
    }

    // ===== pre-barrier: load + convert value/mask -> mv/mf =====
    __syncthreads();     // stage-1 smem reads done before any mv/mf reuse
    {
        const float4* v4 = (const float4*)(value + b*SK*DIM);
        const int4*   m4 = (const int4*)  (mask  + b*SK*DIM);
        float4* mv4 = (float4*)mv;
        float4* mf4 = (float4*)mf;
        #pragma unroll
        for (int j = 0; j < 4; j++) {
            int idx = t + j*256;               // 1024 float4s
            int4 mm = m4[idx]; float4 vv = v4[idx];
            float4 av, af;
            av.x = mm.x ? vv.x : 0.f;  af.x = mm.x ? 1.f : 0.f;
            av.y = mm.y ? vv.y : 0.f;  af.y = mm.y ? 1.f : 0.f;
            av.z = mm.z ? vv.z : 0.f;  af.z = mm.z ? 1.f : 0.f;
            av.w = mm.w ? vv.w : 0.f;  af.w = mm.w ? 1.f : 0.f;
            mv4[idx] = av; mf4[idx] = af;
        }
    }

    // ================= grid barrier =================
    __threadfence();
    __syncthreads();
    if (t == 0) {
        unsigned long long ticket = atomicAdd(&g_bar, 1ULL);
        unsigned long long target = (ticket >> 8) * 256ULL + 256ULL;
        volatile unsigned long long* vb = &g_bar;
        while (*vb < target) { __nanosleep(64); }
        __threadfence();
    }
    __syncthreads();

    // ================= Stage 2: attn + out epilogue =================
    // load ks/qs (proj-dependent; via L2 to dodge stale-L1 across barrier)
    {
        const float4* gk4 = (const float4*)g_k;
        float4* ks4 = (float4*)ks;
        #pragma unroll
        for (int j = 0; j < 8; j++) {
            int idx = t + j*256;               // 2048 float4s
            ks4[idx] = __ldcg(&gk4[b*2048 + idx]);
        }
        qs[t] = __ldcg(&g_q[(b*SQ + q0 + (t>>6))*EV + (t&63)]);
    }
    __syncthreads();

    const float scale = 0.35355339059327373f;   // 1/sqrt(8)

    // phase A: scores + softmax weights.
    // NEW mapping: warp = head (h = t>>5), lanes = (q 0..3, kq 0..7).
    // All 4 q-lanes share the same ks rows -> ks reads dedup 4x.
    // es written as float4 with row stride ESS=136 -> conflict-free.
    {
        int h  = t >> 5;
        int q  = (t >> 3) & 3;
        int kq = t & 7;
        int vr = q*8 + h;             // es row convention unchanged
        int kbase = kq * 16;
        float4 q0r = *(const float4*)&qs[q*EV + h*DKd];
        float4 q1r = *(const float4*)&qs[q*EV + h*DKd + 4];
        u64 qp0 = pack2(q0r.x, q0r.y);
        u64 qp1 = pack2(q0r.z, q0r.w);
        u64 qp2 = pack2(q1r.x, q1r.y);
        u64 qp3 = pack2(q1r.z, q1r.w);

        float s[16];
        #pragma unroll
        for (int i = 0; i < 16; i++) {
            const ulonglong2* kp = (const ulonglong2*)&ks[(kbase+i)*EV + h*DKd];
            ulonglong2 k0 = kp[0], k1 = kp[1];
            u64 a2 = fma2(qp0, k0.x, 0ULL);
            a2 = fma2(qp1, k0.y, a2);
            a2 = fma2(qp2, k1.x, a2);
            a2 = fma2(qp3, k1.y, a2);
            float lo, hi;
            unpack2(a2, lo, hi);
            s[i] = lo + hi;
        }
        float mx = s[0];
        #pragma unroll
        for (int i = 1; i < 16; i++) mx = fmaxf(mx, s[i]);
        mx = fmaxf(mx, __shfl_xor_sync(0xffffffff, mx, 1));
        mx = fmaxf(mx, __shfl_xor_sync(0xffffffff, mx, 2));
        mx = fmaxf(mx, __shfl_xor_sync(0xffffffff, mx, 4));
        float msc = mx * scale;
        #pragma unroll
        for (int i4 = 0; i4 < 4; i4++) {
            float4 ev;
            ev.x = __expf(fmaf(s[i4*4+0], scale, -msc));
            ev.y = __expf(fmaf(s[i4*4+1], scale, -msc));
            ev.z = __expf(fmaf(s[i4*4+2], scale, -msc));
            ev.w = __expf(fmaf(s[i4*4+3], scale, -msc));
            *(float4*)&es[vr*ESS + kbase + i4*4] = ev;
        }
    }
    __syncthreads();   // ks reads done -> xs overlay (on ks) is safe below

    // phase B: num/den accumulate, packed. vr 0..31, dq 0..7 (4 d each)
    float4 xo;
    int vrB = t >> 3, dqB = t & 7;
    {
        u64 n01 = 0, n23 = 0, d01 = 0, d23 = 0;
        const ulonglong2* mv2 = (const ulonglong2*)mv;
        const ulonglong2* mf2 = (const ulonglong2*)mf;
        const float4* ep4 = (const float4*)&es[vrB*ESS];
        #pragma unroll 4
        for (int k4 = 0; k4 < SK/4; k4++) {
            float4 e4 = ep4[k4];
            #pragma unroll
            for (int j = 0; j < 4; j++) {
                float e = (j==0) ? e4.x : (j==1) ? e4.y : (j==2) ? e4.z : e4.w;
                int k = k4*4 + j;
                u64 e2 = pack2(e, e);
                ulonglong2 v = mv2[k*8 + dqB];
                ulonglong2 m = mf2[k*8 + dqB];
                n01 = fma2(e2, v.x, n01);
                n23 = fma2(e2, v.y, n23);
                d01 = fma2(e2, m.x, d01);
                d23 = fma2(e2, m.y, d23);
            }
        }
        float n0,n1,n2,n3, dd0,dd1,dd2,dd3;
        unpack2(n01, n0, n1); unpack2(n23, n2, n3);
        unpack2(d01, dd0, dd1); unpack2(d23, dd2, dd3);
        xo.x = __fdividef(n0, dd0); xo.y = __fdividef(n1, dd1);
        xo.z = __fdividef(n2, dd2); xo.w = __fdividef(n3, dd3);
    }
    {
        int q = vrB >> 3, h = vrB & 7;
        *(float4*)&xs[q*256 + h*DIM + dqB*4] = xo;
    }
    __syncthreads();

    // epilogue: y[q][c] = sum_p xs[q][p] * wo[p][c] + bo[c]
    // thread = (col pair cp, row qsel); packed col-pair FMA, LDG.64 wo.
    {
        int cp   = (t & 63) * 2;
        int qsel = t >> 6;            // 0..3
        u64 acc = pack2(bo[cp], bo[cp+1]);
        const float* xp = &xs[qsel*256];
        #pragma unroll 8
        for (int p = 0; p < 256; p++) {
            u64 w2p = *(const u64*)&wo[p*NH + cp];
            u64 x2  = pack2(xp[p], xp[p]);
            acc = fma2(x2, w2p, acc);
        }
        float r0v, r1v;
        unpack2(acc, r0v, r1v);
        float2 o; o.x = r0v; o.y = r1v;
        *(float2*)&y_out[(b*SQ + q0 + qsel)*NH + cp] = o;
    }
}

// ---------------------------------------------------------------------------
extern "C" void kernel_launch(void* const* d_in, const int* in_sizes, int n_in,
                              void* d_out, int out_size)
{
    bool dictOrder = (in_sizes[4] == Bn*SK*DIM);

    const float *qv, *kv, *val, *imp, *w1, *b1, *w2, *wq, *bq, *wk, *bk,
                *wo, *bo, *wd1, *bd1, *lng, *lnb, *wd2, *bd2;
    const int* mask;

    if (dictOrder) {
        qv  = (const float*)d_in[0];  kv  = (const float*)d_in[1];
        val = (const float*)d_in[2];  imp = (const float*)d_in[3];
        mask= (const int*)  d_in[4];
        w1  = (const float*)d_in[5];  b1  = (const float*)d_in[6];
        w2  = (const float*)d_in[7];
        wq  = (const float*)d_in[8];  bq  = (const float*)d_in[9];
        wk  = (const float*)d_in[10]; bk  = (const float*)d_in[11];
        wo  = (const float*)d_in[12]; bo  = (const float*)d_in[13];
        wd1 = (const float*)d_in[14]; bd1 = (const float*)d_in[15];
        lng = (const float*)d_in[16]; lnb = (const float*)d_in[17];
        wd2 = (const float*)d_in[18]; bd2 = (const float*)d_in[19];
    } else {
        qv  = (const float*)d_in[0];  kv  = (const float*)d_in[1];
        val = (const float*)d_in[2];  imp = (const float*)d_in[3];
        w1  = (const float*)d_in[4];  b1  = (const float*)d_in[5];
        w2  = (const float*)d_in[6];
        wq  = (const float*)d_in[7];  bq  = (const float*)d_in[8];
        wk  = (const float*)d_in[9];  bk  = (const float*)d_in[10];
        wo  = (const float*)d_in[11]; bo  = (const float*)d_in[12];
        wd1 = (const float*)d_in[13]; bd1 = (const float*)d_in[14];
        lng = (const float*)d_in[15]; lnb = (const float*)d_in[16];
        wd2 = (const float*)d_in[17]; bd2 = (const float*)d_in[18];
        mask= (const int*)  d_in[19];
    }

    float* y  = (float*)d_out;                       // [8,128,128]
    float* qd = (float*)d_out + Bn*SQ*NH;            // [8,128,128]

    cudaFuncSetAttribute(mega_kernel,
                         cudaFuncAttributeMaxDynamicSharedMemorySize,
                         20992 * sizeof(float));

    mega_kernel<<<256, 256, 20992 * sizeof(float)>>>(
        qv, kv, val, mask, w1, b1, w2, wq, bq, wk, bk, wo, bo,
        imp, wd1, bd1, lng, lnb, wd2, bd2, y, qd);
}